// round 2
// baseline (speedup 1.0000x reference)
#include <cuda_runtime.h>
#include <cuda_bf16.h>
#include <math.h>

// ---------------- problem constants ----------------
#define BB 2
#define SS 2048
#define DD 1024
#define KF 128      // feature dim K
#define KR 8        // low-rank bypass
#define CC 256      // chunk
#define NCH 8       // S / CC
#define VV 32000
#define MM (BB*SS)  // 4096 rows into the vocab GEMM

static constexpr float LAMBDA = 0.9f;
static constexpr float SCALE  = 0.0883883476483184405501f; // 1/sqrt(128)

// ---------------- scratch (static device globals; no allocation) ----------------
__device__ __align__(16) float g_ctx [BB*SS*DD];   // context-summed embeddings
__device__ __align__(16) float g_h   [BB*SS*DD];   // pre-LN outputs
__device__ __align__(16) float g_hn  [BB*SS*DD];   // post-LN
__device__ __align__(16) float g_q   [BB*CC*KF];
__device__ __align__(16) float g_k   [BB*CC*KF];
__device__ __align__(16) float g_v   [BB*CC*DD];
__device__ __align__(16) float g_u   [BB*CC*DD];   // v - pred
__device__ __align__(16) float g_ot  [BB*CC*DD];   // out before Wo
__device__ __align__(16) float g_attn[BB*CC*CC];
__device__ __align__(16) float g_S   [BB*KF*DD];   // recurrent KV state
__device__ __align__(16) float g_byp [BB*KR];
__device__ __align__(16) float g_St  [BB*DD];
__device__ __align__(16) float g_bias[BB*DD];      // byp@Vb + St (per chunk)

// ---------------- embedding + causal context sum (LCTX=4, mode=sum) ----------------
__global__ void embed_ctx_kernel(const int* __restrict__ x,
                                 const float* __restrict__ emb,
                                 float* __restrict__ ctx)
{
    int bs = blockIdx.x;               // 0 .. B*S-1
    int b  = bs / SS, s = bs % SS;
    int c4 = threadIdx.x;              // 0..255, each handles 4 floats
    float4 acc = make_float4(0.f,0.f,0.f,0.f);
    #pragma unroll
    for (int off = 0; off < 4; off++) {
        int sp = s - off;
        if (sp >= 0) {
            int tok = x[b*SS + sp];
            float4 v = *(const float4*)(emb + (size_t)tok*DD + c4*4);
            acc.x += v.x; acc.y += v.y; acc.z += v.z; acc.w += v.w;
        }
    }
    *(float4*)(ctx + (size_t)bs*DD + c4*4) = acc;
}

// ---------------- generic batched 64x64x16 SGEMM (the scan workhorse) ----------------
// C[bz] = epilogue( alpha * op(A[bz]) @ op(B[bz]) [+ C if ACCUM] )
// EPI: 0 none | 1 phi=elu+1 | 2 causal mask (already includes alpha) | 3 +aux[col] | 4 +aux[row,col]
template<int EPI, bool TRANSA, bool TRANSB, bool ACCUM>
__global__ void __launch_bounds__(256)
gemm64(const float* __restrict__ A, int lda, long long aB,
       const float* __restrict__ Bm, int ldb, long long bB,
       float* __restrict__ Cm, int ldc, long long cB,
       const float* __restrict__ aux, long long auxB,
       int Kdim, float alpha)
{
    __shared__ float As[16][64];
    __shared__ float Bs[16][64];
    int bz = blockIdx.z;
    A  += (size_t)bz * aB;
    Bm += (size_t)bz * bB;
    Cm += (size_t)bz * cB;
    if (EPI == 3 || EPI == 4) aux += (size_t)bz * auxB;

    int m0 = blockIdx.y * 64, n0 = blockIdx.x * 64;
    int t  = threadIdx.x;
    int tx = t & 15, ty = t >> 4;

    float acc[4][4];
    #pragma unroll
    for (int i = 0; i < 4; i++)
        #pragma unroll
        for (int j = 0; j < 4; j++) acc[i][j] = 0.f;

    for (int k0 = 0; k0 < Kdim; k0 += 16) {
        if (!TRANSA) {  // logical A[m][k] = A[(m0+r)*lda + k]
            int r = t >> 2, c = (t & 3) * 4;
            float4 v = *(const float4*)(A + (size_t)(m0 + r)*lda + k0 + c);
            As[c+0][r] = v.x; As[c+1][r] = v.y; As[c+2][r] = v.z; As[c+3][r] = v.w;
        } else {        // logical A[m][k] = Aphys[k][m]  (Aphys rows = k, lda = phys row stride)
            int r = t >> 4, c = (t & 15) * 4;  // r = k offset, c = m offset
            float4 v = *(const float4*)(A + (size_t)(k0 + r)*lda + m0 + c);
            *(float4*)&As[r][c] = v;
        }
        if (!TRANSB) {  // logical B[k][n]
            int r = t >> 4, c = (t & 15) * 4;
            float4 v = *(const float4*)(Bm + (size_t)(k0 + r)*ldb + n0 + c);
            *(float4*)&Bs[r][c] = v;
        } else {        // logical B[k][n] = Bphys[n][k]
            int r = t >> 2, c = (t & 3) * 4;   // r = n offset, c = k offset
            float4 v = *(const float4*)(Bm + (size_t)(n0 + r)*ldb + k0 + c);
            Bs[c+0][r] = v.x; Bs[c+1][r] = v.y; Bs[c+2][r] = v.z; Bs[c+3][r] = v.w;
        }
        __syncthreads();
        #pragma unroll
        for (int kk = 0; kk < 16; kk++) {
            float4 a = *(const float4*)&As[kk][ty*4];
            float4 b = *(const float4*)&Bs[kk][tx*4];
            float av[4] = {a.x, a.y, a.z, a.w};
            float bv[4] = {b.x, b.y, b.z, b.w};
            #pragma unroll
            for (int i = 0; i < 4; i++)
                #pragma unroll
                for (int j = 0; j < 4; j++) acc[i][j] += av[i] * bv[j];
        }
        __syncthreads();
    }

    #pragma unroll
    for (int i = 0; i < 4; i++) {
        int gr = m0 + ty*4 + i;
        #pragma unroll
        for (int j = 0; j < 4; j++) {
            int gc = n0 + tx*4 + j;
            float v = alpha * acc[i][j];
            if (ACCUM)     v += Cm[(size_t)gr*ldc + gc];
            if (EPI == 1)  v = (v > 0.f) ? (v + 1.f) : expf(v);      // phi = elu+1
            if (EPI == 2)  v = (gc <= gr) ? v : 0.f;                  // causal (alpha=scale)
            if (EPI == 3)  v += aux[gc];                              // + bias vector
            if (EPI == 4)  v += aux[(size_t)gr*ldc + gc];             // + src matrix
            Cm[(size_t)gr*ldc + gc] = v;
        }
    }
}

// ---------------- per-chunk small state kernels ----------------
__global__ void bias_prep_kernel(const float* __restrict__ byp,
                                 const float* __restrict__ Vb,
                                 const float* __restrict__ St,
                                 float* __restrict__ bias)
{
    int b = blockIdx.x;
    float w[KR];
    #pragma unroll
    for (int r = 0; r < KR; r++) w[r] = byp[b*KR + r];
    for (int d = threadIdx.x; d < DD; d += blockDim.x) {
        float v = St[b*DD + d];
        #pragma unroll
        for (int r = 0; r < KR; r++) v += w[r] * Vb[r*DD + d];
        bias[b*DD + d] = v;
    }
}

__global__ void state_update_kernel(const float* __restrict__ ctx, int n,
                                    const float* __restrict__ Ub,
                                    float* __restrict__ byp,
                                    float* __restrict__ St)
{
    __shared__ float xs[DD];
    int b = blockIdx.x;
    int t = threadIdx.x;                 // 256 threads, 4 floats each
    const float* base = ctx + ((size_t)b*SS + (size_t)n*CC) * DD;
    float4 acc = make_float4(0.f,0.f,0.f,0.f);
    for (int i = 0; i < CC; i++) {
        float4 v = *(const float4*)(base + (size_t)i*DD + t*4);
        acc.x += v.x; acc.y += v.y; acc.z += v.z; acc.w += v.w;
    }
    const float inv = 1.0f / CC;
    acc.x *= inv; acc.y *= inv; acc.z *= inv; acc.w *= inv;
    xs[t*4+0] = acc.x; xs[t*4+1] = acc.y; xs[t*4+2] = acc.z; xs[t*4+3] = acc.w;

    float4 st = *(float4*)(St + b*DD + t*4);
    st.x = LAMBDA*st.x + (1.f-LAMBDA)*acc.x;
    st.y = LAMBDA*st.y + (1.f-LAMBDA)*acc.y;
    st.z = LAMBDA*st.z + (1.f-LAMBDA)*acc.z;
    st.w = LAMBDA*st.w + (1.f-LAMBDA)*acc.w;
    *(float4*)(St + b*DD + t*4) = st;

    __syncthreads();
    int w = t >> 5, lane = t & 31;       // 8 warps: warp w computes byp[b][w]
    float s = 0.f;
    for (int d = lane; d < DD; d += 32) s += xs[d] * Ub[d*KR + w];
    #pragma unroll
    for (int o = 16; o; o >>= 1) s += __shfl_xor_sync(0xffffffffu, s, o);
    if (lane == 0) byp[b*KR + w] = s;
}

// ---------------- LayerNorm ----------------
__global__ void ln_kernel(const float* __restrict__ h,
                          const float* __restrict__ gam,
                          const float* __restrict__ bet,
                          float* __restrict__ hn)
{
    __shared__ float red[8];
    int bs = blockIdx.x, t = threadIdx.x;
    const float* row = h + (size_t)bs*DD;
    float4 v = *(const float4*)(row + t*4);

    float s = v.x + v.y + v.z + v.w;
    #pragma unroll
    for (int o = 16; o; o >>= 1) s += __shfl_xor_sync(0xffffffffu, s, o);
    if ((t & 31) == 0) red[t >> 5] = s;
    __syncthreads();
    float mu = (red[0]+red[1]+red[2]+red[3]+red[4]+red[5]+red[6]+red[7]) * (1.0f/DD);
    __syncthreads();

    float d0 = v.x-mu, d1 = v.y-mu, d2 = v.z-mu, d3 = v.w-mu;
    float sq = d0*d0 + d1*d1 + d2*d2 + d3*d3;
    #pragma unroll
    for (int o = 16; o; o >>= 1) sq += __shfl_xor_sync(0xffffffffu, sq, o);
    if ((t & 31) == 0) red[t >> 5] = sq;
    __syncthreads();
    float var = (red[0]+red[1]+red[2]+red[3]+red[4]+red[5]+red[6]+red[7]) * (1.0f/DD);
    float rs = rsqrtf(var + 1e-5f);

    float4 g4 = *(const float4*)(gam + t*4);
    float4 b4 = *(const float4*)(bet + t*4);
    float4 o;
    o.x = d0*rs*g4.x + b4.x;
    o.y = d1*rs*g4.y + b4.y;
    o.z = d2*rs*g4.z + b4.z;
    o.w = d3*rs*g4.w + b4.w;
    *(float4*)(hn + (size_t)bs*DD + t*4) = o;
}

// ---------------- logits: 128x128x8 SGEMM, double-buffered smem ----------------
// C[4096,32000] = hn[4096,1024] @ Wout[1024,32000] + bout
// One __syncthreads per k-step (prefetch gmem->regs, compute buf cur, store buf nxt).
__global__ void __launch_bounds__(256)
sgemm_logits(const float* __restrict__ A,
             const float* __restrict__ B,
             const float* __restrict__ bias,
             float* __restrict__ C)
{
    __shared__ float As[2][8][128];
    __shared__ float Bs[2][8][128];
    int m0 = blockIdx.x * 128;     // x over M -> Wout streams from DRAM once, A stays in L2
    int n0 = blockIdx.y * 128;
    int t  = threadIdx.x;
    int tx = t & 15, ty = t >> 4;

    int ar = t >> 1,  ac = (t & 1)  * 4;   // 128 rows x 8 cols
    int br = t >> 5,  bc = (t & 31) * 4;   // 8 rows x 128 cols
    const float* Aptr = A + (size_t)(m0 + ar)*DD + ac;
    const float* Bptr = B + (size_t)br*VV + n0 + bc;

    float acc[8][8];
    #pragma unroll
    for (int i = 0; i < 8; i++)
        #pragma unroll
        for (int j = 0; j < 8; j++) acc[i][j] = 0.f;

    // preload tile 0 into buffer 0
    float4 va = *(const float4*)Aptr;  Aptr += 8;
    float4 vb = *(const float4*)Bptr;  Bptr += (size_t)8*VV;
    As[0][ac+0][ar] = va.x; As[0][ac+1][ar] = va.y;
    As[0][ac+2][ar] = va.z; As[0][ac+3][ar] = va.w;
    *(float4*)&Bs[0][br][bc] = vb;
    __syncthreads();

    int cur = 0;
    #pragma unroll 4
    for (int k0 = 8; k0 < DD; k0 += 8) {
        // prefetch next tile to registers (overlaps with compute below)
        va = *(const float4*)Aptr;  Aptr += 8;
        vb = *(const float4*)Bptr;  Bptr += (size_t)8*VV;

        #pragma unroll
        for (int kk = 0; kk < 8; kk++) {
            float a[8], b[8];
            *(float4*)&a[0] = *(const float4*)&As[cur][kk][ty*4];
            *(float4*)&a[4] = *(const float4*)&As[cur][kk][64 + ty*4];
            *(float4*)&b[0] = *(const float4*)&Bs[cur][kk][tx*4];
            *(float4*)&b[4] = *(const float4*)&Bs[cur][kk][64 + tx*4];
            #pragma unroll
            for (int i = 0; i < 8; i++)
                #pragma unroll
                for (int j = 0; j < 8; j++) acc[i][j] += a[i] * b[j];
        }

        int nxt = cur ^ 1;
        As[nxt][ac+0][ar] = va.x; As[nxt][ac+1][ar] = va.y;
        As[nxt][ac+2][ar] = va.z; As[nxt][ac+3][ar] = va.w;
        *(float4*)&Bs[nxt][br][bc] = vb;
        __syncthreads();
        cur = nxt;
    }

    // last tile
    #pragma unroll
    for (int kk = 0; kk < 8; kk++) {
        float a[8], b[8];
        *(float4*)&a[0] = *(const float4*)&As[cur][kk][ty*4];
        *(float4*)&a[4] = *(const float4*)&As[cur][kk][64 + ty*4];
        *(float4*)&b[0] = *(const float4*)&Bs[cur][kk][tx*4];
        *(float4*)&b[4] = *(const float4*)&Bs[cur][kk][64 + tx*4];
        #pragma unroll
        for (int i = 0; i < 8; i++)
            #pragma unroll
            for (int j = 0; j < 8; j++) acc[i][j] += a[i] * b[j];
    }

    float bias0[4], bias1[4];
    *(float4*)bias0 = *(const float4*)(bias + n0 + tx*4);
    *(float4*)bias1 = *(const float4*)(bias + n0 + 64 + tx*4);

    #pragma unroll
    for (int i = 0; i < 8; i++) {
        int gr = m0 + ((i < 4) ? (ty*4 + i) : (64 + ty*4 + (i-4)));
        float* Crow = C + (size_t)gr*VV + n0;
        float4 o;
        o.x = acc[i][0] + bias0[0];
        o.y = acc[i][1] + bias0[1];
        o.z = acc[i][2] + bias0[2];
        o.w = acc[i][3] + bias0[3];
        *(float4*)(Crow + tx*4) = o;
        o.x = acc[i][4] + bias1[0];
        o.y = acc[i][5] + bias1[1];
        o.z = acc[i][6] + bias1[2];
        o.w = acc[i][7] + bias1[3];
        *(float4*)(Crow + 64 + tx*4) = o;
    }
}

// ---------------- launch ----------------
extern "C" void kernel_launch(void* const* d_in, const int* in_sizes, int n_in,
                              void* d_out, int out_size)
{
    (void)in_sizes; (void)n_in; (void)out_size;
    const int*   x    = (const int*)  d_in[0];
    const float* emb  = (const float*)d_in[1];
    const float* Wq   = (const float*)d_in[2];
    const float* Wk   = (const float*)d_in[3];
    const float* Wv   = (const float*)d_in[4];
    const float* Wo   = (const float*)d_in[5];
    const float* Ub   = (const float*)d_in[6];
    const float* Vb   = (const float*)d_in[7];
    const float* lng  = (const float*)d_in[8];
    const float* lnb  = (const float*)d_in[9];
    const float* Wout = (const float*)d_in[10];
    const float* bout = (const float*)d_in[11];
    float* out = (float*)d_out;

    float *ctx, *h, *hn, *q, *k, *v, *u, *ot, *attn, *Sst, *byp, *St, *bias;
    cudaGetSymbolAddress((void**)&ctx,  g_ctx);
    cudaGetSymbolAddress((void**)&h,    g_h);
    cudaGetSymbolAddress((void**)&hn,   g_hn);
    cudaGetSymbolAddress((void**)&q,    g_q);
    cudaGetSymbolAddress((void**)&k,    g_k);
    cudaGetSymbolAddress((void**)&v,    g_v);
    cudaGetSymbolAddress((void**)&u,    g_u);
    cudaGetSymbolAddress((void**)&ot,   g_ot);
    cudaGetSymbolAddress((void**)&attn, g_attn);
    cudaGetSymbolAddress((void**)&Sst,  g_S);
    cudaGetSymbolAddress((void**)&byp,  g_byp);
    cudaGetSymbolAddress((void**)&St,   g_St);
    cudaGetSymbolAddress((void**)&bias, g_bias);

    // zero the recurrent carry (deterministic per call)
    cudaMemsetAsync(Sst, 0, sizeof(float)*BB*KF*DD);
    cudaMemsetAsync(byp, 0, sizeof(float)*BB*KR);
    cudaMemsetAsync(St,  0, sizeof(float)*BB*DD);

    embed_ctx_kernel<<<BB*SS, 256>>>(x, emb, ctx);

    const long long aBx = (long long)SS*DD;   // ctx batch stride
    const long long qkB = (long long)CC*KF;
    const long long vB  = (long long)CC*DD;
    const long long SB  = (long long)KF*DD;

    for (int n = 0; n < NCH; n++) {
        const float* xc = ctx + (size_t)n*CC*DD;
        // q = phi(xc @ Wq), k = phi(xc @ Wk)
        gemm64<1,false,false,false><<<dim3(KF/64, CC/64, BB), 256>>>(
            xc, DD, aBx, Wq, KF, 0, q, KF, qkB, nullptr, 0, DD, 1.f);
        gemm64<1,false,false,false><<<dim3(KF/64, CC/64, BB), 256>>>(
            xc, DD, aBx, Wk, KF, 0, k, KF, qkB, nullptr, 0, DD, 1.f);
        // v = xc @ Wv
        gemm64<0,false,false,false><<<dim3(DD/64, CC/64, BB), 256>>>(
            xc, DD, aBx, Wv, DD, 0, v, DD, vB, nullptr, 0, DD, 1.f);
        // bias[b][d] = byp@Vb + St  (carry from previous chunk)
        bias_prep_kernel<<<BB, 256>>>(byp, Vb, St, bias);
        // attn = tril(q k^T) * scale
        gemm64<2,false,true,false><<<dim3(CC/64, CC/64, BB), 256>>>(
            q, KF, qkB, k, KF, qkB, attn, CC, (long long)CC*CC, nullptr, 0, KF, SCALE);
        // ot = attn @ v + bias
        gemm64<3,false,false,false><<<dim3(DD/64, CC/64, BB), 256>>>(
            attn, CC, (long long)CC*CC, v, DD, vB, ot, DD, vB, bias, (long long)DD, CC, 1.f);
        // ot += scale * q @ S    (old S)
        gemm64<0,false,false,true><<<dim3(DD/64, CC/64, BB), 256>>>(
            q, KF, qkB, Sst, DD, SB, ot, DD, vB, nullptr, 0, KF, SCALE);
        // u = v - scale * k @ S  (old S)
        gemm64<4,false,false,false><<<dim3(DD/64, CC/64, BB), 256>>>(
            k, KF, qkB, Sst, DD, SB, u, DD, vB, v, vB, KF, -SCALE);
        // S += k^T @ u
        gemm64<0,true,false,true><<<dim3(DD/64, KF/64, BB), 256>>>(
            k, KF, qkB, u, DD, vB, Sst, DD, SB, nullptr, 0, CC, 1.f);
        // h_chunk = ot @ Wo
        gemm64<0,false,false,false><<<dim3(DD/64, CC/64, BB), 256>>>(
            ot, DD, vB, Wo, DD, 0, h + (size_t)n*CC*DD, DD, aBx, nullptr, 0, DD, 1.f);
        // xmean -> byp, St for next chunk
        state_update_kernel<<<BB, 256>>>(ctx, n, Ub, byp, St);
    }

    ln_kernel<<<BB*SS, 256>>>(h, lng, lnb, hn);
    sgemm_logits<<<dim3(MM/128, VV/128), 256>>>(hn, Wout, bout, out);
}

// round 7
// speedup vs baseline: 1.9745x; 1.9745x over previous
#include <cuda_runtime.h>
#include <cuda_bf16.h>
#include <math.h>
#include <stdint.h>

// ---------------- problem constants ----------------
#define BB 2
#define SS 2048
#define DD 1024
#define KF 128      // feature dim K
#define KR 8        // low-rank bypass
#define CC 256      // chunk
#define NCH 8       // S / CC
#define VV 32000
#define MM (BB*SS)  // 4096 rows into the vocab GEMM
#define K3 3072     // split-3 contraction length for the logits GEMM

static constexpr float LAMBDA = 0.9f;
static constexpr float SCALE  = 0.0883883476483184405501f; // 1/sqrt(128)

// ---------------- scratch (static device globals; no allocation) ----------------
__device__ __align__(16) float g_ctx [BB*SS*DD];    // context-summed embeddings
__device__ __align__(16) float g_h   [BB*SS*DD];    // pre-LN outputs
__device__ __align__(16) float g_q   [(size_t)MM*KF];   // phi(ctx@Wq), all chunks
__device__ __align__(16) float g_k   [(size_t)MM*KF];   // phi(ctx@Wk), all chunks
__device__ __align__(16) float g_v   [BB*SS*DD];    // ctx@Wv, all chunks
__device__ __align__(16) float g_ot  [BB*SS*DD];    // out accumulator, all chunks
__device__ __align__(16) float g_u   [BB*CC*DD];    // v - pred (per chunk)
__device__ __align__(16) float g_attn[(size_t)BB*NCH*CC*CC];
__device__ __align__(16) float g_S   [BB*KF*DD];    // recurrent KV state
__device__ __align__(16) float g_byp [BB*KR];
__device__ __align__(16) float g_St  [BB*DD];
__device__ __align__(16) float g_bias[BB*DD];       // byp@Vb + St (per chunk)
// split-3 bf16 operands for the tensor-core logits GEMM
__device__ __align__(16) __nv_bfloat16 g_A3[(size_t)MM*K3];  // [4096,3072] = [hi|hi|lo] of ln(h)
__device__ __align__(16) __nv_bfloat16 g_B3[(size_t)VV*K3];  // [32000,3072] = [hi|lo|hi] of Wout^T

// ---------------- PTX helpers (sm_80-compatible only; target is plain sm_103) ----------------
__device__ __forceinline__ uint32_t smem_u32(const void* p) {
    uint32_t a;
    asm("{ .reg .u64 t; cvta.to.shared.u64 t, %1; cvt.u32.u64 %0, t; }" : "=r"(a) : "l"(p));
    return a;
}
__device__ __forceinline__ void cp_async16(uint32_t dst, const void* src) {
    asm volatile("cp.async.cg.shared.global [%0], [%1], 16;\n" :: "r"(dst), "l"(src));
}
#define CP_COMMIT() asm volatile("cp.async.commit_group;\n" ::: "memory")

__device__ __forceinline__ void ldsm_x4(uint32_t& r0, uint32_t& r1, uint32_t& r2, uint32_t& r3,
                                        uint32_t addr) {
    asm volatile("ldmatrix.sync.aligned.m8n8.x4.shared.b16 {%0,%1,%2,%3}, [%4];"
                 : "=r"(r0), "=r"(r1), "=r"(r2), "=r"(r3) : "r"(addr));
}
__device__ __forceinline__ void mma16816(float* c, const uint32_t* a, uint32_t b0, uint32_t b1) {
    asm volatile("mma.sync.aligned.m16n8k16.row.col.f32.bf16.bf16.f32 "
                 "{%0,%1,%2,%3}, {%4,%5,%6,%7}, {%8,%9}, {%0,%1,%2,%3};"
                 : "+f"(c[0]), "+f"(c[1]), "+f"(c[2]), "+f"(c[3])
                 : "r"(a[0]), "r"(a[1]), "r"(a[2]), "r"(a[3]), "r"(b0), "r"(b1));
}

// ---------------- embedding + causal context sum (LCTX=4, mode=sum) ----------------
__global__ void embed_ctx_kernel(const int* __restrict__ x,
                                 const float* __restrict__ emb,
                                 float* __restrict__ ctx)
{
    int bs = blockIdx.x;               // 0 .. B*S-1
    int b  = bs / SS, s = bs % SS;
    int c4 = threadIdx.x;              // 0..255, each handles 4 floats
    float4 acc = make_float4(0.f,0.f,0.f,0.f);
    #pragma unroll
    for (int off = 0; off < 4; off++) {
        int sp = s - off;
        if (sp >= 0) {
            int tok = x[b*SS + sp];
            float4 v = *(const float4*)(emb + (size_t)tok*DD + c4*4);
            acc.x += v.x; acc.y += v.y; acc.z += v.z; acc.w += v.w;
        }
    }
    *(float4*)(ctx + (size_t)bs*DD + c4*4) = acc;
}

// ---------------- generic batched 64x64x16 SGEMM (the scan workhorse) ----------------
// C[bz] = epilogue( alpha * op(A[bz]) @ op(B[bz]) [+ C if ACCUM] )
// EPI: 0 none | 1 phi=elu+1 | 2 causal mask | 3 +aux[col] | 4 +aux[row,col]
template<int EPI, bool TRANSA, bool TRANSB, bool ACCUM>
__global__ void __launch_bounds__(256)
gemm64(const float* __restrict__ A, int lda, long long aB,
       const float* __restrict__ Bm, int ldb, long long bB,
       float* __restrict__ Cm, int ldc, long long cB,
       const float* __restrict__ aux, long long auxB,
       int Kdim, float alpha)
{
    __shared__ float As[16][64];
    __shared__ float Bs[16][64];
    int bz = blockIdx.z;
    A  += (size_t)bz * aB;
    Bm += (size_t)bz * bB;
    Cm += (size_t)bz * cB;
    if (EPI == 3 || EPI == 4) aux += (size_t)bz * auxB;

    int m0 = blockIdx.y * 64, n0 = blockIdx.x * 64;
    int t  = threadIdx.x;
    int tx = t & 15, ty = t >> 4;

    float acc[4][4];
    #pragma unroll
    for (int i = 0; i < 4; i++)
        #pragma unroll
        for (int j = 0; j < 4; j++) acc[i][j] = 0.f;

    for (int k0 = 0; k0 < Kdim; k0 += 16) {
        if (!TRANSA) {
            int r = t >> 2, c = (t & 3) * 4;
            float4 v = *(const float4*)(A + (size_t)(m0 + r)*lda + k0 + c);
            As[c+0][r] = v.x; As[c+1][r] = v.y; As[c+2][r] = v.z; As[c+3][r] = v.w;
        } else {
            int r = t >> 4, c = (t & 15) * 4;
            float4 v = *(const float4*)(A + (size_t)(k0 + r)*lda + m0 + c);
            *(float4*)&As[r][c] = v;
        }
        if (!TRANSB) {
            int r = t >> 4, c = (t & 15) * 4;
            float4 v = *(const float4*)(Bm + (size_t)(k0 + r)*ldb + n0 + c);
            *(float4*)&Bs[r][c] = v;
        } else {
            int r = t >> 2, c = (t & 3) * 4;
            float4 v = *(const float4*)(Bm + (size_t)(n0 + r)*ldb + k0 + c);
            Bs[c+0][r] = v.x; Bs[c+1][r] = v.y; Bs[c+2][r] = v.z; Bs[c+3][r] = v.w;
        }
        __syncthreads();
        #pragma unroll
        for (int kk = 0; kk < 16; kk++) {
            float4 a = *(const float4*)&As[kk][ty*4];
            float4 b = *(const float4*)&Bs[kk][tx*4];
            float av[4] = {a.x, a.y, a.z, a.w};
            float bv[4] = {b.x, b.y, b.z, b.w};
            #pragma unroll
            for (int i = 0; i < 4; i++)
                #pragma unroll
                for (int j = 0; j < 4; j++) acc[i][j] += av[i] * bv[j];
        }
        __syncthreads();
    }

    #pragma unroll
    for (int i = 0; i < 4; i++) {
        int gr = m0 + ty*4 + i;
        #pragma unroll
        for (int j = 0; j < 4; j++) {
            int gc = n0 + tx*4 + j;
            float v = alpha * acc[i][j];
            if (ACCUM)     v += Cm[(size_t)gr*ldc + gc];
            if (EPI == 1)  v = (v > 0.f) ? (v + 1.f) : expf(v);      // phi = elu+1
            if (EPI == 2)  v = (gc <= gr) ? v : 0.f;                  // causal (alpha=scale)
            if (EPI == 3)  v += aux[gc];                              // + bias vector
            if (EPI == 4)  v += aux[(size_t)gr*ldc + gc];             // + src matrix
            Cm[(size_t)gr*ldc + gc] = v;
        }
    }
}

// ---------------- per-chunk small state kernels ----------------
__global__ void bias_prep_kernel(const float* __restrict__ byp,
                                 const float* __restrict__ Vb,
                                 const float* __restrict__ St,
                                 float* __restrict__ bias)
{
    int b = blockIdx.x;
    float w[KR];
    #pragma unroll
    for (int r = 0; r < KR; r++) w[r] = byp[b*KR + r];
    for (int d = threadIdx.x; d < DD; d += blockDim.x) {
        float v = St[b*DD + d];
        #pragma unroll
        for (int r = 0; r < KR; r++) v += w[r] * Vb[r*DD + d];
        bias[b*DD + d] = v;
    }
}

__global__ void state_update_kernel(const float* __restrict__ ctx, int n,
                                    const float* __restrict__ Ub,
                                    float* __restrict__ byp,
                                    float* __restrict__ St)
{
    __shared__ float xs[DD];
    int b = blockIdx.x;
    int t = threadIdx.x;
    const float* base = ctx + ((size_t)b*SS + (size_t)n*CC) * DD;
    float4 acc = make_float4(0.f,0.f,0.f,0.f);
    for (int i = 0; i < CC; i++) {
        float4 v = *(const float4*)(base + (size_t)i*DD + t*4);
        acc.x += v.x; acc.y += v.y; acc.z += v.z; acc.w += v.w;
    }
    const float inv = 1.0f / CC;
    acc.x *= inv; acc.y *= inv; acc.z *= inv; acc.w *= inv;
    xs[t*4+0] = acc.x; xs[t*4+1] = acc.y; xs[t*4+2] = acc.z; xs[t*4+3] = acc.w;

    float4 st = *(float4*)(St + b*DD + t*4);
    st.x = LAMBDA*st.x + (1.f-LAMBDA)*acc.x;
    st.y = LAMBDA*st.y + (1.f-LAMBDA)*acc.y;
    st.z = LAMBDA*st.z + (1.f-LAMBDA)*acc.z;
    st.w = LAMBDA*st.w + (1.f-LAMBDA)*acc.w;
    *(float4*)(St + b*DD + t*4) = st;

    __syncthreads();
    int w = t >> 5, lane = t & 31;
    float s = 0.f;
    for (int d = lane; d < DD; d += 32) s += xs[d] * Ub[d*KR + w];
    #pragma unroll
    for (int o = 16; o; o >>= 1) s += __shfl_xor_sync(0xffffffffu, s, o);
    if (lane == 0) byp[b*KR + w] = s;
}

// ---------------- LayerNorm + split into bf16 A3 = [hi|hi|lo] ----------------
__global__ void ln_split_kernel(const float* __restrict__ h,
                                const float* __restrict__ gam,
                                const float* __restrict__ bet,
                                __nv_bfloat16* __restrict__ A3)
{
    __shared__ float red[8];
    int bs = blockIdx.x, t = threadIdx.x;
    const float* row = h + (size_t)bs*DD;
    float4 v = *(const float4*)(row + t*4);

    float s = v.x + v.y + v.z + v.w;
    #pragma unroll
    for (int o = 16; o; o >>= 1) s += __shfl_xor_sync(0xffffffffu, s, o);
    if ((t & 31) == 0) red[t >> 5] = s;
    __syncthreads();
    float mu = (red[0]+red[1]+red[2]+red[3]+red[4]+red[5]+red[6]+red[7]) * (1.0f/DD);
    __syncthreads();

    float d0 = v.x-mu, d1 = v.y-mu, d2 = v.z-mu, d3 = v.w-mu;
    float sq = d0*d0 + d1*d1 + d2*d2 + d3*d3;
    #pragma unroll
    for (int o = 16; o; o >>= 1) sq += __shfl_xor_sync(0xffffffffu, sq, o);
    if ((t & 31) == 0) red[t >> 5] = sq;
    __syncthreads();
    float var = (red[0]+red[1]+red[2]+red[3]+red[4]+red[5]+red[6]+red[7]) * (1.0f/DD);
    float rs = rsqrtf(var + 1e-5f);

    float4 g4 = *(const float4*)(gam + t*4);
    float4 b4 = *(const float4*)(bet + t*4);
    float o[4];
    o[0] = d0*rs*g4.x + b4.x;
    o[1] = d1*rs*g4.y + b4.y;
    o[2] = d2*rs*g4.z + b4.z;
    o[3] = d3*rs*g4.w + b4.w;

    __nv_bfloat16* dst = A3 + (size_t)bs*K3 + t*4;
    #pragma unroll
    for (int j = 0; j < 4; j++) {
        __nv_bfloat16 hi = __float2bfloat16(o[j]);
        __nv_bfloat16 lo = __float2bfloat16(o[j] - __bfloat162float(hi));
        dst[j]           = hi;   // segment 0: hi
        dst[DD + j]      = hi;   // segment 1: hi (pairs with b_lo)
        dst[2*DD + j]    = lo;   // segment 2: lo (pairs with b_hi)
    }
}

// ---------------- Wout transpose + split into bf16 B3 = [hi|lo|hi] ----------------
// Wout [1024, 32000] row-major -> B3 [32000, 3072]
__global__ void wout_split_kernel(const float* __restrict__ W,
                                  __nv_bfloat16* __restrict__ B3)
{
    __shared__ float tile[32][33];
    int n0 = blockIdx.x * 32, k0 = blockIdx.y * 32;
    int tx = threadIdx.x, ty = threadIdx.y;   // 32 x 8
    #pragma unroll
    for (int i = 0; i < 4; i++) {
        int k = k0 + ty + i*8;
        tile[ty + i*8][tx] = W[(size_t)k*VV + n0 + tx];
    }
    __syncthreads();
    int t  = ty*32 + tx;      // 0..255
    int nl = t >> 3;          // 0..31
    int kq = (t & 7) * 4;     // 0,4,...,28
    __nv_bfloat16* dst = B3 + (size_t)(n0 + nl)*K3 + k0 + kq;
    #pragma unroll
    for (int j = 0; j < 4; j++) {
        float a = tile[kq + j][nl];
        __nv_bfloat16 hi = __float2bfloat16(a);
        __nv_bfloat16 lo = __float2bfloat16(a - __bfloat162float(hi));
        dst[j]          = hi;   // segment 0: hi
        dst[DD + j]     = lo;   // segment 1: lo (pairs with a_hi)
        dst[2*DD + j]   = hi;   // segment 2: hi (pairs with a_lo)
    }
}

// ---------------- logits GEMM via mma.sync bf16 ----------------
// C[4096,32000] = A3[4096,3072] @ B3[32000,3072]^T + bout
// CTA tile 128x128, 8 warps (each 32 rows x 64 cols), K chunk = 32 bf16, 4-stage cp.async.
#define LG_STAGES 4
#define LG_NIT    (K3/32)        // 96 k-chunks
#define LG_STG_SZ 8192           // 128 rows x 64 B per operand stage
#define LG_B_OFF  (LG_STAGES*LG_STG_SZ)   // 32768
#define LG_SMEM   (2*LG_STAGES*LG_STG_SZ) // 65536

// swizzled offset within a stage: row*64 + (chunk ^ ((row>>1)&3))*16
__device__ __forceinline__ uint32_t lg_swz(int row, int chunk) {
    return (uint32_t)(row*64 + ((chunk ^ ((row >> 1) & 3)) << 4));
}

__device__ __forceinline__ void lg_load(uint32_t sb, int s, int kc,
                                        const __nv_bfloat16* Ab,
                                        const __nv_bfloat16* Bb, int t)
{
    uint32_t abase = sb + s*LG_STG_SZ;
    uint32_t bbase = sb + LG_B_OFF + s*LG_STG_SZ;
    const char* Ag = (const char*)Ab + (size_t)kc*64;   // 32 bf16 = 64 B per row-chunk
    const char* Bg = (const char*)Bb + (size_t)kc*64;
    #pragma unroll
    for (int j = 0; j < 2; j++) {
        int i = t + 256*j;
        int r = i >> 2, c = i & 3;
        cp_async16(abase + lg_swz(r, c), Ag + (size_t)r*(K3*2) + c*16);
    }
    #pragma unroll
    for (int j = 0; j < 2; j++) {
        int i = t + 256*j;
        int r = i >> 2, c = i & 3;
        cp_async16(bbase + lg_swz(r, c), Bg + (size_t)r*(K3*2) + c*16);
    }
}

__global__ void __launch_bounds__(256)
logits_mma_kernel(const __nv_bfloat16* __restrict__ A3,
                  const __nv_bfloat16* __restrict__ B3,
                  const float* __restrict__ bout,
                  float* __restrict__ C)
{
    extern __shared__ char smem[];
    uint32_t sb = smem_u32(smem);
    int t = threadIdx.x, wid = t >> 5, lane = t & 31;
    int m0 = blockIdx.x * 128;     // x fastest over M: B3 block shared by 32 consecutive CTAs
    int n0 = blockIdx.y * 128;
    int wm = wid & 3, wn = wid >> 2;

    const __nv_bfloat16* Ab = A3 + (size_t)m0 * K3;
    const __nv_bfloat16* Bb = B3 + (size_t)n0 * K3;

    float acc[2][8][4];
    #pragma unroll
    for (int i = 0; i < 2; i++)
        #pragma unroll
        for (int j = 0; j < 8; j++)
            #pragma unroll
            for (int q = 0; q < 4; q++) acc[i][j][q] = 0.f;

    #pragma unroll
    for (int s = 0; s < LG_STAGES - 1; s++) { lg_load(sb, s, s, Ab, Bb, t); CP_COMMIT(); }

    // per-lane ldmatrix address components
    int a_row = lane & 15;              // + wm*32 + mt*16
    int a_ch  = lane >> 4;              // + 2*ks
    int b_row = (lane & 7) + ((lane >> 4) << 3);  // lanes 0-7 -> rows 0-7, 16-31 -> rows 8-15
    int b_ch  = (lane >> 3) & 1;        // + 2*ks

    for (int kc = 0; kc < LG_NIT; kc++) {
        int s = kc & (LG_STAGES - 1);
        if (kc < LG_NIT - 2) asm volatile("cp.async.wait_group 2;\n" ::: "memory");
        else                 asm volatile("cp.async.wait_group 0;\n" ::: "memory");
        __syncthreads();
        if (kc + LG_STAGES - 1 < LG_NIT) {
            lg_load(sb, (kc + LG_STAGES - 1) & (LG_STAGES - 1), kc + LG_STAGES - 1, Ab, Bb, t);
            CP_COMMIT();
        }
        uint32_t aS = sb + s*LG_STG_SZ;
        uint32_t bS = sb + LG_B_OFF + s*LG_STG_SZ;
        #pragma unroll
        for (int ks = 0; ks < 2; ks++) {
            uint32_t a[2][4];
            #pragma unroll
            for (int mt = 0; mt < 2; mt++) {
                int row = wm*32 + mt*16 + a_row;
                ldsm_x4(a[mt][0], a[mt][1], a[mt][2], a[mt][3],
                        aS + lg_swz(row, 2*ks + a_ch));
            }
            #pragma unroll
            for (int nt2 = 0; nt2 < 4; nt2++) {
                int row = wn*64 + nt2*16 + b_row;
                uint32_t b0, b1, b2, b3;
                ldsm_x4(b0, b1, b2, b3, bS + lg_swz(row, 2*ks + b_ch));
                #pragma unroll
                for (int mt = 0; mt < 2; mt++) {
                    mma16816(acc[mt][2*nt2+0], a[mt], b0, b1);
                    mma16816(acc[mt][2*nt2+1], a[mt], b2, b3);
                }
            }
        }
    }

    // epilogue: c0,c1 -> (m = lane/4, n = 2*(lane%4)+{0,1}); c2,c3 -> m+8
    int mr = lane >> 2, nc2 = (lane & 3) * 2;
    #pragma unroll
    for (int mt = 0; mt < 2; mt++) {
        int r0 = m0 + wm*32 + mt*16 + mr;
        #pragma unroll
        for (int nt = 0; nt < 8; nt++) {
            int col = n0 + wn*64 + nt*8 + nc2;
            float bx = bout[col], by = bout[col + 1];
            float2 v0 = make_float2(acc[mt][nt][0] + bx, acc[mt][nt][1] + by);
            float2 v1 = make_float2(acc[mt][nt][2] + bx, acc[mt][nt][3] + by);
            *(float2*)(C + (size_t)r0*VV + col)       = v0;
            *(float2*)(C + (size_t)(r0 + 8)*VV + col) = v1;
        }
    }
}

// ---------------- launch ----------------
extern "C" void kernel_launch(void* const* d_in, const int* in_sizes, int n_in,
                              void* d_out, int out_size)
{
    (void)in_sizes; (void)n_in; (void)out_size;
    const int*   x    = (const int*)  d_in[0];
    const float* emb  = (const float*)d_in[1];
    const float* Wq   = (const float*)d_in[2];
    const float* Wk   = (const float*)d_in[3];
    const float* Wv   = (const float*)d_in[4];
    const float* Wo   = (const float*)d_in[5];
    const float* Ub   = (const float*)d_in[6];
    const float* Vb   = (const float*)d_in[7];
    const float* lng  = (const float*)d_in[8];
    const float* lnb  = (const float*)d_in[9];
    const float* Wout = (const float*)d_in[10];
    const float* bout = (const float*)d_in[11];
    float* out = (float*)d_out;

    float *ctx, *h, *q, *k, *v, *u, *ot, *attn, *Sst, *byp, *St, *bias;
    __nv_bfloat16 *A3, *B3;
    cudaGetSymbolAddress((void**)&ctx,  g_ctx);
    cudaGetSymbolAddress((void**)&h,    g_h);
    cudaGetSymbolAddress((void**)&q,    g_q);
    cudaGetSymbolAddress((void**)&k,    g_k);
    cudaGetSymbolAddress((void**)&v,    g_v);
    cudaGetSymbolAddress((void**)&u,    g_u);
    cudaGetSymbolAddress((void**)&ot,   g_ot);
    cudaGetSymbolAddress((void**)&attn, g_attn);
    cudaGetSymbolAddress((void**)&Sst,  g_S);
    cudaGetSymbolAddress((void**)&byp,  g_byp);
    cudaGetSymbolAddress((void**)&St,   g_St);
    cudaGetSymbolAddress((void**)&bias, g_bias);
    cudaGetSymbolAddress((void**)&A3,   g_A3);
    cudaGetSymbolAddress((void**)&B3,   g_B3);

    cudaFuncSetAttribute(logits_mma_kernel,
                         cudaFuncAttributeMaxDynamicSharedMemorySize, LG_SMEM);

    // zero the recurrent carry (deterministic per call)
    cudaMemsetAsync(Sst, 0, sizeof(float)*BB*KF*DD);
    cudaMemsetAsync(byp, 0, sizeof(float)*BB*KR);
    cudaMemsetAsync(St,  0, sizeof(float)*BB*DD);

    embed_ctx_kernel<<<BB*SS, 256>>>(x, emb, ctx);
    // B3 does not depend on the scan — build it early
    wout_split_kernel<<<dim3(VV/32, DD/32), dim3(32, 8)>>>(Wout, B3);

    // ---- hoisted S-independent work (big parallel launches) ----
    // Q = phi(ctx@Wq), K = phi(ctx@Wk) over all 4096 rows
    gemm64<1,false,false,false><<<dim3(KF/64, MM/64, 1), 256>>>(
        ctx, DD, 0, Wq, KF, 0, q, KF, 0, nullptr, 0, DD, 1.f);
    gemm64<1,false,false,false><<<dim3(KF/64, MM/64, 1), 256>>>(
        ctx, DD, 0, Wk, KF, 0, k, KF, 0, nullptr, 0, DD, 1.f);
    // V = ctx@Wv over all rows
    gemm64<0,false,false,false><<<dim3(DD/64, MM/64, 1), 256>>>(
        ctx, DD, 0, Wv, DD, 0, v, DD, 0, nullptr, 0, DD, 1.f);
    // attn[z] = tril(q_z k_z^T)*scale for all 16 chunks (z = b*NCH + n; offset z*CC*KF valid
    // because b*SS*KF = b*NCH*CC*KF)
    gemm64<2,false,true,false><<<dim3(CC/64, CC/64, BB*NCH), 256>>>(
        q, KF, (long long)CC*KF, k, KF, (long long)CC*KF,
        attn, CC, (long long)CC*CC, nullptr, 0, KF, SCALE);
    // ot[z] = attn[z] @ v_z (intra-chunk part)
    gemm64<0,false,false,false><<<dim3(DD/64, CC/64, BB*NCH), 256>>>(
        attn, CC, (long long)CC*CC, v, DD, (long long)CC*DD,
        ot, DD, (long long)CC*DD, nullptr, 0, CC, 1.f);

    // ---- sequential recurrence (S-dependent only) ----
    const long long qkB = (long long)SS*KF;   // per-b stride within full Q/K
    const long long vBs = (long long)SS*DD;   // per-b stride within full V/OT
    const long long SB  = (long long)KF*DD;
    for (int n = 0; n < NCH; n++) {
        bias_prep_kernel<<<BB, 256>>>(byp, Vb, St, bias);
        // ot += scale * q @ S + bias
        gemm64<3,false,false,true><<<dim3(DD/64, CC/64, BB), 256>>>(
            q + (size_t)n*CC*KF, KF, qkB, Sst, DD, SB,
            ot + (size_t)n*CC*DD, DD, vBs, bias, (long long)DD, KF, SCALE);
        // u = v - scale * k @ S
        gemm64<4,false,false,false><<<dim3(DD/64, CC/64, BB), 256>>>(
            k + (size_t)n*CC*KF, KF, qkB, Sst, DD, SB,
            u, DD, (long long)CC*DD, v + (size_t)n*CC*DD, vBs, KF, -SCALE);
        // S += k^T @ u
        gemm64<0,true,false,true><<<dim3(DD/64, KF/64, BB), 256>>>(
            k + (size_t)n*CC*KF, KF, qkB, u, DD, (long long)CC*DD,
            Sst, DD, SB, nullptr, 0, CC, 1.f);
        state_update_kernel<<<BB, 256>>>(ctx, n, Ub, byp, St);
    }

    // h = ot @ Wo over all rows
    gemm64<0,false,false,false><<<dim3(DD/64, MM/64, 1), 256>>>(
        ot, DD, 0, Wo, DD, 0, h, DD, 0, nullptr, 0, DD, 1.f);

    ln_split_kernel<<<BB*SS, 256>>>(h, lng, lnb, A3);
    logits_mma_kernel<<<dim3(MM/128, VV/128), 256, LG_SMEM>>>(A3, B3, bout, out);
}